// round 15
// baseline (speedup 1.0000x reference)
#include <cuda_runtime.h>

// ---------------------------------------------------------------------------
// GATNet: 2-layer GAT, N=50000, E=800000 (+N self loops).
// R14 -> R15: scatter-RMW replaced by CSR gather-aggregation.
//  - CSR by dst (src-only entries, self-loops pre-slotted, shfl-scan).
//  - k_agg: warp/node; 32-edge chunks compute w coalesced (one exp/edge),
//    shfl-broadcast gather of float2 feature rows; denom reduced in-warp
//    and divided inline. No feature atomics, no acc zeroing, no g_d arrays.
//  - R6's CSR "failure" was actually its transposed GEMMs (R7 measured
//    410us); tiled GEMMs are kept from R13/R14.
//  - gemm1/k_out keep float4 smem inner loops; gemm1 at profile slot 3.
// ---------------------------------------------------------------------------

#define N_NODES 50000
#define F_IN    128
#define HID     64
#define C_OUT   121
#define E_RAW   800000
#define E_TOT   (E_RAW + N_NODES)
#define NB      ((N_NODES + 63) / 64)     // 782 node-tile blocks

// Scratch (static device globals -- allocation is forbidden)
__device__ __align__(8)  int2  g_sd[E_RAW];               // packed (src,dst)
__device__ int   g_is32;
__device__ int   g_cnt[N_NODES];                          // counts -> cursors
__device__ int   g_rowptr[N_NODES + 1];
__device__ int   g_csr_src[E_TOT];                        // src per CSR slot
__device__ __align__(16) float g_h1   [N_NODES * HID];    // x @ W1
__device__ __align__(16) float g_acc1 [N_NODES * HID];    // layer1 agg (normalized)
__device__ __align__(16) float g_hrelu[N_NODES * HID];    // relu(acc1 + b1)
__device__ __align__(16) float g_acc2 [N_NODES * HID];    // layer2 agg (normalized)
__device__ float g_as[N_NODES];
__device__ float g_ad[N_NODES];
__device__ float g_vs[HID];                               // W2 @ a_src2
__device__ float g_vd[HID];                               // W2 @ a_dst2

// ---------------- histogram init (self-loop slot) ---------------------------
__global__ void k_histinit() {
    const int i = blockIdx.x * blockDim.x + threadIdx.x;
    if (i < N_NODES) g_cnt[i] = 1;
}

// ---------------- dtype detection -------------------------------------------
// int64 ids < 2^31 -> every odd 32-bit word is 0; int32 -> random ids.
__global__ void k_detect(const unsigned* __restrict__ ei32) {
    __shared__ int found;
    if (threadIdx.x == 0) found = 0;
    __syncthreads();
    int local = 0;
    for (int k = threadIdx.x; k < 4096; k += blockDim.x) {
        const int j = k * (E_RAW / 4096);
        if (ei32[2 * j + 1] != 0u) local = 1;
    }
    if (local) found = 1;
    __syncthreads();
    if (threadIdx.x == 0) g_is32 = found;
}

// ---------------- convert indices + histogram by dst ------------------------
__global__ void k_convert_hist(const void* __restrict__ ei) {
    const int stride = gridDim.x * blockDim.x;
    const int i0 = blockIdx.x * blockDim.x + threadIdx.x;
    for (int i = i0; i < E_RAW; i += stride) {
        int s, d;
        if (g_is32) {
            s = ((const int*)ei)[i];
            d = ((const int*)ei)[E_RAW + i];
        } else {
            s = (int)((const long long*)ei)[i];
            d = (int)((const long long*)ei)[E_RAW + i];
        }
        g_sd[i] = make_int2(s, d);
        atomicAdd(&g_cnt[d], 1);
    }
}

// ---------------- GEMM 1 (tiled): h1 = x @ W1, alphas -----------------------
// 64 nodes/block, 256 threads; thread = 4 nodes x 4 feats; float4 LDS loads.
__global__ void k_gemm1(const float* __restrict__ x,
                        const float* __restrict__ W1,
                        const float* __restrict__ a_src,
                        const float* __restrict__ a_dst) {
    __shared__ __align__(16) float xs[64 * 36];   // [node][kk], stride 36
    __shared__ __align__(16) float ws[32 * 64];   // [kk][f]
    const int tid = threadIdx.x;
    const int n0  = blockIdx.x * 64;
    const int nb  = tid >> 4;
    const int fg  = tid & 15;
    float4 acc[4];
    acc[0] = acc[1] = acc[2] = acc[3] = make_float4(0.f, 0.f, 0.f, 0.f);

    for (int kt = 0; kt < 4; kt++) {
        __syncthreads();
        for (int l = tid; l < 64 * 32; l += 256) {
            const int row = l >> 5, col = l & 31;
            const int node = n0 + row;
            xs[row * 36 + col] = (node < N_NODES)
                ? x[node * F_IN + kt * 32 + col] : 0.f;
        }
        for (int l = tid; l < 32 * 64; l += 256)
            ws[l] = W1[kt * 2048 + l];
        __syncthreads();
#pragma unroll
        for (int kk = 0; kk < 32; kk += 4) {
            float4 xv[4];
#pragma unroll
            for (int i = 0; i < 4; i++)
                xv[i] = *(const float4*)(xs + (nb * 4 + i) * 36 + kk);
#pragma unroll
            for (int j = 0; j < 4; j++) {
                const float4 wv = *(const float4*)(ws + (kk + j) * 64 + fg * 4);
#pragma unroll
                for (int i = 0; i < 4; i++) {
                    const float xj = ((const float*)&xv[i])[j];
                    acc[i].x += xj * wv.x; acc[i].y += xj * wv.y;
                    acc[i].z += xj * wv.z; acc[i].w += xj * wv.w;
                }
            }
        }
    }

    const float4 s4 = *(const float4*)(a_src + fg * 4);
    const float4 d4 = *(const float4*)(a_dst + fg * 4);
    float ps[4], pd[4];
#pragma unroll
    for (int i = 0; i < 4; i++) {
        ps[i] = acc[i].x * s4.x + acc[i].y * s4.y + acc[i].z * s4.z + acc[i].w * s4.w;
        pd[i] = acc[i].x * d4.x + acc[i].y * d4.y + acc[i].z * d4.z + acc[i].w * d4.w;
    }
#pragma unroll
    for (int off = 8; off > 0; off >>= 1) {
#pragma unroll
        for (int i = 0; i < 4; i++) {
            ps[i] += __shfl_down_sync(0xffffffffu, ps[i], off, 16);
            pd[i] += __shfl_down_sync(0xffffffffu, pd[i], off, 16);
        }
    }
#pragma unroll
    for (int i = 0; i < 4; i++) {
        const int node = n0 + nb * 4 + i;
        if (node < N_NODES) {
            *(float4*)(g_h1 + node * HID + fg * 4) = acc[i];
            if (fg == 0) { g_as[node] = ps[i]; g_ad[node] = pd[i]; }
        }
    }
}

// ---------------- scan + self-loop placement --------------------------------
// Exclusive scan of g_cnt -> g_rowptr (single 1024-thread block), then
// self loop into slot 0 of each row and cursor reset.
__global__ void k_scan_self() {
    __shared__ int woff[32];
    __shared__ int carry, chunk_total;
    const int t = threadIdx.x, lane = t & 31, wid = t >> 5;
    if (t == 0) carry = 0;
    __syncthreads();
    for (int base = 0; base < N_NODES; base += 1024) {
        const int i = base + t;
        const int v = (i < N_NODES) ? g_cnt[i] : 0;
        int incl = v;
#pragma unroll
        for (int off = 1; off < 32; off <<= 1) {
            int y = __shfl_up_sync(0xffffffffu, incl, off);
            if (lane >= off) incl += y;
        }
        if (lane == 31) woff[wid] = incl;
        __syncthreads();
        if (wid == 0) {
            int s = woff[lane];
            int si = s;
#pragma unroll
            for (int off = 1; off < 32; off <<= 1) {
                int y = __shfl_up_sync(0xffffffffu, si, off);
                if (lane >= off) si += y;
            }
            woff[lane] = si - s;
            if (lane == 31) chunk_total = si;
        }
        __syncthreads();
        if (i < N_NODES) {
            const int rp = carry + woff[wid] + incl - v;
            g_rowptr[i] = rp;
            g_csr_src[rp] = i;      // self loop at slot 0
            g_cnt[i] = 1;           // cursor
        }
        __syncthreads();
        if (t == 0) carry += chunk_total;
        __syncthreads();
    }
    if (t == 0) g_rowptr[N_NODES] = carry;   // == E_TOT
}

// ---------------- fill CSR --------------------------------------------------
__global__ void k_fill() {
    const int i = blockIdx.x * blockDim.x + threadIdx.x;
    if (i >= E_RAW) return;
    const int2 sd = g_sd[i];
    const int p = g_rowptr[sd.y] + atomicAdd(&g_cnt[sd.y], 1);
    g_csr_src[p] = sd.x;
}

// ---------------- precompute v_s = W2 a_src2, v_d = W2 a_dst2 ---------------
__global__ void k_prep2(const float* __restrict__ W2,
                        const float* __restrict__ a_src2,
                        const float* __restrict__ a_dst2) {
    const int t = threadIdx.x;         // 0..127
    const int k = t & 63;
    const float* a = (t < 64) ? a_src2 : a_dst2;
    float acc = 0.f;
    for (int f = 0; f < C_OUT; f++) acc += W2[k * C_OUT + f] * a[f];
    if (t < 64) g_vs[k] = acc; else g_vd[k] = acc;
}

// ---------------- CSR aggregation: warp per node ----------------------------
// 32-edge chunks: each lane computes w for one edge (coalesced csr loads,
// one exp per edge), then shfl-broadcast loop gathers float2 feature rows.
// Softmax denominator reduced in-warp; division fused into the store.
__global__ void k_agg(int layer) {
    const int warp = threadIdx.x >> 5;
    const int lane = threadIdx.x & 31;
    const int node = blockIdx.x * 8 + warp;   // grid*8 == N_NODES exactly
    const float* feat = layer ? g_hrelu : g_h1;
    float*       accо = layer ? g_acc2  : g_acc1;
    const int beg = g_rowptr[node];
    const int end = g_rowptr[node + 1];
    const float ad_n = g_ad[node];
    float ax = 0.f, ay = 0.f, wsum = 0.f;
    for (int base = beg; base < end; base += 32) {
        const int e = base + lane;
        int s = 0; float w = 0.f;
        if (e < end) {
            s = g_csr_src[e];
            float lg = g_as[s] + ad_n;
            lg = (lg > 0.f) ? lg : 0.2f * lg;   // leaky_relu 0.2
            w = __expf(lg);
            wsum += w;
        }
        const int cnt = min(32, end - base);
        for (int j = 0; j < cnt; j++) {
            const int   sj = __shfl_sync(0xffffffffu, s, j);
            const float wj = __shfl_sync(0xffffffffu, w, j);
            const float2 h = *(const float2*)(feat + sj * HID + lane * 2);
            ax += wj * h.x; ay += wj * h.y;
        }
    }
#pragma unroll
    for (int off = 16; off > 0; off >>= 1)
        wsum += __shfl_xor_sync(0xffffffffu, wsum, off);
    const float inv = 1.f / wsum;
    ((float2*)accо)[node * (HID / 2) + lane] = make_float2(ax * inv, ay * inv);
}

// ---------------- node pass: hrelu = relu(acc1 + b1); alphas2 ---------------
__global__ void k_hrelu(const float* __restrict__ b1) {
    const int node = blockIdx.x * 8 + (threadIdx.x >> 5);
    if (node >= N_NODES) return;
    const int lane = threadIdx.x & 31;
    float2 a = ((const float2*)g_acc1)[node * (HID / 2) + lane];
    const float2 b = ((const float2*)b1)[lane];
    float hx = a.x + b.x;
    float hy = a.y + b.y;
    hx = hx > 0.f ? hx : 0.f;
    hy = hy > 0.f ? hy : 0.f;
    ((float2*)g_hrelu)[node * (HID / 2) + lane] = make_float2(hx, hy);
    const float2 vs = ((const float2*)g_vs)[lane];
    const float2 vd = ((const float2*)g_vd)[lane];
    float ps = hx * vs.x + hy * vs.y;
    float pd = hx * vd.x + hy * vd.y;
#pragma unroll
    for (int off = 16; off > 0; off >>= 1) {
        ps += __shfl_down_sync(0xffffffffu, ps, off);
        pd += __shfl_down_sync(0xffffffffu, pd, off);
    }
    if (lane == 0) { g_as[node] = ps; g_ad[node] = pd; }
}

// ---------------- output GEMM: out = sigmoid(acc2 @ W2 + b2) ----------------
// 64 nodes/block, 256 threads; thread = 4 nodes x 8 feats; float4 hs loads.
__global__ void k_out(const float* __restrict__ W2,
                      const float* __restrict__ b2,
                      float* __restrict__ out) {
    __shared__ __align__(16) float hs [64 * 64];   // [node][k]
    __shared__ __align__(16) float ws2[64 * 128];  // [k][f] zero-padded
    const int tid = threadIdx.x;
    const int n0  = blockIdx.x * 64;
    const int nb  = tid >> 4;
    const int fg  = tid & 15;
    for (int l = tid; l < 64 * 64; l += 256) {
        const int node = n0 + (l >> 6);
        const int k = l & 63;
        hs[l] = (node < N_NODES) ? g_acc2[node * HID + k] : 0.f;
    }
    for (int l = tid; l < 64 * 128; l += 256) {
        const int k = l >> 7, f = l & 127;
        ws2[l] = (f < C_OUT) ? W2[k * C_OUT + f] : 0.f;
    }
    __syncthreads();

    float4 acc[4][2];
#pragma unroll
    for (int i = 0; i < 4; i++) {
        acc[i][0] = make_float4(0.f, 0.f, 0.f, 0.f);
        acc[i][1] = make_float4(0.f, 0.f, 0.f, 0.f);
    }
#pragma unroll
    for (int kk = 0; kk < 64; kk += 4) {
        float4 xv[4];
#pragma unroll
        for (int i = 0; i < 4; i++)
            xv[i] = *(const float4*)(hs + (nb * 4 + i) * 64 + kk);
#pragma unroll
        for (int j = 0; j < 4; j++) {
            const float4 w0 = *(const float4*)(ws2 + (kk + j) * 128 + fg * 8);
            const float4 w1 = *(const float4*)(ws2 + (kk + j) * 128 + fg * 8 + 4);
#pragma unroll
            for (int i = 0; i < 4; i++) {
                const float xj = ((const float*)&xv[i])[j];
                acc[i][0].x += xj * w0.x; acc[i][0].y += xj * w0.y;
                acc[i][0].z += xj * w0.z; acc[i][0].w += xj * w0.w;
                acc[i][1].x += xj * w1.x; acc[i][1].y += xj * w1.y;
                acc[i][1].z += xj * w1.z; acc[i][1].w += xj * w1.w;
            }
        }
    }

#pragma unroll
    for (int i = 0; i < 4; i++) {
        const int node = n0 + nb * 4 + i;
        if (node >= N_NODES) continue;
        const float* a = (const float*)&acc[i][0];
#pragma unroll
        for (int j = 0; j < 8; j++) {
            const int f = fg * 8 + j;
            if (f < C_OUT) {
                const float v = a[j] + b2[f];
                out[node * C_OUT + f] = 1.f / (1.f + __expf(-v));
            }
        }
    }
}

// ---------------------------------------------------------------------------
extern "C" void kernel_launch(void* const* d_in, const int* in_sizes, int n_in,
                              void* d_out, int out_size) {
    const float* x      = (const float*)d_in[0];
    const void*  ei     = d_in[1];
    const float* W1     = (const float*)d_in[2];
    const float* a_src1 = (const float*)d_in[3];
    const float* a_dst1 = (const float*)d_in[4];
    const float* b1     = (const float*)d_in[5];
    const float* W2     = (const float*)d_in[6];
    const float* a_src2 = (const float*)d_in[7];
    const float* a_dst2 = (const float*)d_in[8];
    const float* b2     = (const float*)d_in[9];
    float*       out    = (float*)d_out;

    const int TPB = 256;
    const int gN = (N_NODES + TPB - 1) / TPB;
    const int gE = (E_RAW + TPB - 1) / TPB;

    k_histinit<<<gN, TPB>>>();                               // 0
    k_detect<<<1, 256>>>((const unsigned*)ei);               // 1
    k_convert_hist<<<1024, TPB>>>(ei);                       // 2
    k_gemm1<<<NB, 256>>>(x, W1, a_src1, a_dst1);             // 3  <- profiled
    k_scan_self<<<1, 1024>>>();                              // 4
    k_fill<<<gE, TPB>>>();                                   // 5
    k_prep2<<<1, 128>>>(W2, a_src2, a_dst2);                 // 6

    // ----- Layer 1 aggregation -----
    k_agg<<<N_NODES / 8, TPB>>>(0);                          // 7
    k_hrelu<<<(N_NODES + 7) / 8, TPB>>>(b1);                 // 8

    // ----- Layer 2 aggregation -----
    k_agg<<<N_NODES / 8, TPB>>>(1);                          // 9

    // ----- Output GEMM + sigmoid -----
    k_out<<<NB, 256>>>(W2, b2, out);                         // 10
}